// round 1
// baseline (speedup 1.0000x reference)
#include <cuda_runtime.h>
#include <cuda_bf16.h>

// Problem constants
// B=8, T=1024 (32x32), C=512, H=4 heads, GROUPS=32 (16 ch/group)
// qkvT layout: [6144 features][8192 bt], feature = head*1536 + c*3 + i (i=0:q,1:k,2:v)

#define NB 8
#define NT 1024
#define NC 512
#define NH 4
#define BT (NB*NT)          // 8192
#define NQKV (NH*NC*3)      // 6144

// ---------------- scratch (device globals; no cudaMalloc allowed) ----------------
__device__ float g_h[BT * NC];                       // 16.8 MB  groupnormed input [bt][c]
__device__ float g_qkvT[(long long)NQKV * BT];       // 201 MB   [feature][bt]
__device__ float g_attn[32 * NC * NC];               // 33.5 MB  [b*4+h][c][d]
__device__ float g_av[32 * NC * NT];                 // 67 MB    [b*4+h][c][t]
__device__ float g_mean[NB * 32];
__device__ float g_rstd[NB * 32];

// ---------------- GroupNorm stats: one block per (b, group) ----------------
__global__ void gn_stats(const float* __restrict__ x) {
    int bg = blockIdx.x;                 // b*32 + g
    int b = bg >> 5, g = bg & 31;
    const float* base = x + (size_t)b * (NT * NC) + g * 16;
    float s = 0.f, ss = 0.f;
    for (int idx = threadIdx.x; idx < NT * 16; idx += 256) {
        float v = base[(idx >> 4) * NC + (idx & 15)];
        s += v; ss += v * v;
    }
    // warp reduce
    for (int o = 16; o; o >>= 1) {
        s  += __shfl_xor_sync(0xffffffffu, s,  o);
        ss += __shfl_xor_sync(0xffffffffu, ss, o);
    }
    __shared__ float sa[8], sb[8];
    int wid = threadIdx.x >> 5;
    if ((threadIdx.x & 31) == 0) { sa[wid] = s; sb[wid] = ss; }
    __syncthreads();
    if (threadIdx.x == 0) {
        float S = 0.f, SS = 0.f;
        #pragma unroll
        for (int i = 0; i < 8; i++) { S += sa[i]; SS += sb[i]; }
        float inv = 1.0f / (NT * 16);
        float mean = S * inv;
        float var  = SS * inv - mean * mean;
        g_mean[bg] = mean;
        g_rstd[bg] = rsqrtf(var + 1e-5f);
    }
}

// ---------------- GroupNorm apply ----------------
__global__ void gn_apply(const float* __restrict__ x,
                         const float* __restrict__ scale,
                         const float* __restrict__ bias) {
    int idx = blockIdx.x * 256 + threadIdx.x;   // over BT*NC = 4194304
    if (idx >= BT * NC) return;
    int c = idx & (NC - 1);
    int b = idx >> 19;                          // / (1024*512)
    int bg = b * 32 + (c >> 4);
    g_h[idx] = (x[idx] - g_mean[bg]) * g_rstd[bg] * scale[c] + bias[c];
}

// ---------------- generic-stride batched SGEMM: C[m,n] = alpha * sum_k A[m,k]B[k,n] (+bias_m +bias_n +resid) ----------------
// 128x128 block tile, BK=8, 256 threads, 8x8 per-thread micro-tile.
// All M,N multiples of 128 and K multiples of 8 in this problem -> no bounds checks.
__global__ void __launch_bounds__(256, 2)
sgemm128(const float* __restrict__ A, const float* __restrict__ B,
         float* __restrict__ C,
         int K,
         long long Asm, long long Ask,
         long long Bsk, long long Bsn,
         long long Csm, long long Csn,
         int zInner,
         long long Abi, long long Abo,
         long long Bbi, long long Bbo,
         long long Cbi, long long Cbo,
         float alpha,
         const float* __restrict__ bias_m,
         const float* __restrict__ bias_n,
         const float* __restrict__ resid) {
    const int BM = 128, BN = 128, BK = 8;
    __shared__ float As[BK][BM];
    __shared__ float Bs[BK][BN];

    int z = blockIdx.z;
    int zi = z % zInner, zo = z / zInner;
    A += zi * Abi + zo * Abo;
    B += zi * Bbi + zo * Bbo;
    long long cbase = zi * Cbi + zo * Cbo;

    int m0 = blockIdx.y * BM;
    int n0 = blockIdx.x * BN;
    int tid = threadIdx.x;
    int tx = tid & 15, ty = tid >> 4;

    float acc[8][8];
    #pragma unroll
    for (int i = 0; i < 8; i++)
        #pragma unroll
        for (int j = 0; j < 8; j++) acc[i][j] = 0.f;

    for (int k0 = 0; k0 < K; k0 += BK) {
        #pragma unroll
        for (int i = 0; i < 4; i++) {
            int li = tid + i * 256;
            int m = li & (BM - 1);
            int kk = li >> 7;
            As[kk][m] = A[(long long)(m0 + m) * Asm + (long long)(k0 + kk) * Ask];
        }
        #pragma unroll
        for (int i = 0; i < 4; i++) {
            int li = tid + i * 256;
            int n = li & (BN - 1);
            int kk = li >> 7;
            Bs[kk][n] = B[(long long)(k0 + kk) * Bsk + (long long)(n0 + n) * Bsn];
        }
        __syncthreads();
        #pragma unroll
        for (int kk = 0; kk < BK; kk++) {
            float a[8], bb[8];
            #pragma unroll
            for (int i = 0; i < 8; i++) a[i] = As[kk][ty * 8 + i];
            #pragma unroll
            for (int j = 0; j < 8; j++) bb[j] = Bs[kk][tx * 8 + j];
            #pragma unroll
            for (int i = 0; i < 8; i++)
                #pragma unroll
                for (int j = 0; j < 8; j++) acc[i][j] += a[i] * bb[j];
        }
        __syncthreads();
    }

    #pragma unroll
    for (int i = 0; i < 8; i++) {
        int m = m0 + ty * 8 + i;
        float bm = bias_m ? bias_m[m] : 0.f;
        #pragma unroll
        for (int j = 0; j < 8; j++) {
            int n = n0 + tx * 8 + j;
            float v = acc[i][j] * alpha + bm;
            if (bias_n) v += bias_n[n];
            long long off = cbase + (long long)m * Csm + (long long)n * Csn;
            if (resid) v += resid[off];
            C[off] = v;
        }
    }
}

// ---------------- softmax over last axis (rows of 512) ----------------
__global__ void softmax512(float* __restrict__ a) {
    float* row = a + (size_t)blockIdx.x * NC;
    int tid = threadIdx.x;
    float v0 = row[tid], v1 = row[tid + 256];
    float m = fmaxf(v0, v1);
    __shared__ float red[8];
    for (int o = 16; o; o >>= 1) m = fmaxf(m, __shfl_xor_sync(0xffffffffu, m, o));
    if ((tid & 31) == 0) red[tid >> 5] = m;
    __syncthreads();
    m = red[0];
    #pragma unroll
    for (int i = 1; i < 8; i++) m = fmaxf(m, red[i]);
    __syncthreads();
    float e0 = __expf(v0 - m), e1 = __expf(v1 - m);
    float s = e0 + e1;
    for (int o = 16; o; o >>= 1) s += __shfl_xor_sync(0xffffffffu, s, o);
    if ((tid & 31) == 0) red[tid >> 5] = s;
    __syncthreads();
    s = 0.f;
    #pragma unroll
    for (int i = 0; i < 8; i++) s += red[i];
    float inv = 1.0f / s;
    row[tid] = e0 * inv;
    row[tid + 256] = e1 * inv;
}

extern "C" void kernel_launch(void* const* d_in, const int* in_sizes, int n_in,
                              void* d_out, int out_size) {
    const float* x        = (const float*)d_in[0];
    const float* gn_scale = (const float*)d_in[1];
    const float* gn_bias  = (const float*)d_in[2];
    const float* w_qkv    = (const float*)d_in[3];
    const float* b_qkv    = (const float*)d_in[4];
    const float* w_out    = (const float*)d_in[5];
    const float* b_out    = (const float*)d_in[6];
    float* out = (float*)d_out;

    float *h, *qkvT, *attn, *av;
    cudaGetSymbolAddress((void**)&h,    g_h);
    cudaGetSymbolAddress((void**)&qkvT, g_qkvT);
    cudaGetSymbolAddress((void**)&attn, g_attn);
    cudaGetSymbolAddress((void**)&av,   g_av);

    // 1) GroupNorm
    gn_stats<<<NB * 32, 256>>>(x);
    gn_apply<<<(BT * NC) / 256, 256>>>(x, gn_scale, gn_bias);

    // 2) QKV projection, output transposed: qkvT[feature=m][bt=n]
    //    A[m,k] = w_qkv[k*6144 + m]; B[k,n] = h[n*512 + k]
    sgemm128<<<dim3(BT / 128, NQKV / 128, 1), 256>>>(
        w_qkv, h, qkvT, NC,
        /*Asm*/1, /*Ask*/NQKV,
        /*Bsk*/1, /*Bsn*/NC,
        /*Csm*/BT, /*Csn*/1,
        1, 0, 0, 0, 0, 0, 0,
        1.0f, b_qkv, nullptr, nullptr);

    // 3) logits[c,d] = (1/32) sum_t Q[c,t] K[d,t], batch z=b*4+h (zi=h, zo=b)
    //    Q[c,t] = qkvT[(h*1536 + c*3 + 0)*8192 + b*1024 + t]
    sgemm128<<<dim3(NC / 128, NC / 128, 32), 256>>>(
        qkvT, qkvT + BT /* +1 feature row => K */, attn, NT,
        /*Asm*/3LL * BT, /*Ask*/1,
        /*Bsk*/1, /*Bsn*/3LL * BT,
        /*Csm*/NC, /*Csn*/1,
        /*zInner*/NH,
        /*Abi(h)*/1536LL * BT, /*Abo(b)*/NT,
        /*Bbi*/1536LL * BT,    /*Bbo*/NT,
        /*Cbi*/ (long long)NC * NC, /*Cbo*/4LL * NC * NC,
        1.0f / 32.0f, nullptr, nullptr, nullptr);

    // 4) softmax over d
    softmax512<<<32 * NC, 256>>>(attn);

    // 5) av[c,t] = sum_d P[c,d] V[d,t]
    sgemm128<<<dim3(NT / 128, NC / 128, 32), 256>>>(
        attn, qkvT + 2 * BT /* V */, av, NC,
        /*Asm*/NC, /*Ask*/1,
        /*Bsk*/3LL * BT, /*Bsn*/1,
        /*Csm*/NT, /*Csn*/1,
        /*zInner*/NH,
        /*Abi*/(long long)NC * NC, /*Abo*/4LL * NC * NC,
        /*Bbi*/1536LL * BT,        /*Bbo*/NT,
        /*Cbi*/(long long)NC * NT, /*Cbo*/4LL * NC * NT,
        1.0f, nullptr, nullptr, nullptr);

    // 6) out[b,t,c] = sum_k av[b, k, t] * w_out[k, c] + b_out[c] + x[b,t,c]
    //    batch over b; A[m=t, k] = av[b][k*1024 + t]
    sgemm128<<<dim3(NC / 128, NT / 128, NB), 256>>>(
        av, w_out, out, NH * NC,
        /*Asm*/1, /*Ask*/NT,
        /*Bsk*/NC, /*Bsn*/1,
        /*Csm*/NC, /*Csn*/1,
        /*zInner*/1,
        0, /*Abo(b)*/4LL * NC * NT,
        0, 0,
        0, /*Cbo(b)*/(long long)NT * NC,
        1.0f, nullptr, b_out, x);
}

// round 3
// speedup vs baseline: 4.0598x; 4.0598x over previous
#include <cuda_runtime.h>
#include <cstdint>

#define NB 8
#define NT 1024
#define NC 512
#define NH 4
#define BT (NB*NT)          // 8192
#define NF 2048             // NH*NC

// ---------------- scratch (device globals) ----------------
__device__ float g_h[BT * NC];                     // groupnormed [bt][c]
__device__ float g_qkT[(long long)2 * NF * BT];    // rows: [0..2047]=Q(h*512+c), [2048..4095]=K ; [row][bt]
__device__ float g_v2[(long long)BT * NF];         // [bt][h*512+d]
__device__ float g_attn[32 * NC * NC];             // [b*4+h][c][d]
__device__ float g_av2[(long long)BT * NF];        // [bt][h*512+c]
__device__ float g_wqkT[6144 * NC];                // [row][c] row: sec*2048 + h*512 + c
__device__ float g_woutT[NC * NF];                 // [c][f]
__device__ float g_bqkT[6144];
__device__ float g_mean[NB * 32];
__device__ float g_rstd[NB * 32];

// ---------------- GroupNorm ----------------
__global__ void gn_stats(const float* __restrict__ x) {
    int bg = blockIdx.x;
    int b = bg >> 5, g = bg & 31;
    const float* base = x + (size_t)b * (NT * NC) + g * 16;
    float s = 0.f, ss = 0.f;
    for (int idx = threadIdx.x; idx < NT * 16; idx += 256) {
        float v = base[(idx >> 4) * NC + (idx & 15)];
        s += v; ss += v * v;
    }
    for (int o = 16; o; o >>= 1) {
        s  += __shfl_xor_sync(0xffffffffu, s,  o);
        ss += __shfl_xor_sync(0xffffffffu, ss, o);
    }
    __shared__ float sa[8], sb[8];
    int wid = threadIdx.x >> 5;
    if ((threadIdx.x & 31) == 0) { sa[wid] = s; sb[wid] = ss; }
    __syncthreads();
    if (threadIdx.x == 0) {
        float S = 0.f, SS = 0.f;
        #pragma unroll
        for (int i = 0; i < 8; i++) { S += sa[i]; SS += sb[i]; }
        float inv = 1.0f / (NT * 16);
        float mean = S * inv;
        float var  = SS * inv - mean * mean;
        g_mean[bg] = mean;
        g_rstd[bg] = rsqrtf(var + 1e-5f);
    }
}

__global__ void gn_apply(const float* __restrict__ x,
                         const float* __restrict__ scale,
                         const float* __restrict__ bias) {
    int idx = blockIdx.x * 256 + threadIdx.x;
    if (idx >= BT * NC) return;
    int c = idx & (NC - 1);
    int b = idx >> 19;
    int bg = b * 32 + (c >> 4);
    g_h[idx] = (x[idx] - g_mean[bg]) * g_rstd[bg] * scale[c] + bias[c];
}

// ---------------- weight transposes ----------------
// wT[row][k]: row = sec*2048 + h*512 + c  maps to src feature f = h*1536 + 3c + sec
__global__ void tr_wqkv(const float* __restrict__ w, float* __restrict__ wT) {
    __shared__ float t[32][33];
    int blk = blockIdx.x;             // 0..191
    int sec = blk >> 6;               // /64
    int within = blk & 63;
    int h = within >> 4, ct = within & 15;
    int c0 = ct * 32;
    int fbase = h * 1536 + sec;
    int r0 = sec * 2048 + h * 512 + c0;
    int tx = threadIdx.x & 31, ty = threadIdx.x >> 5;
    for (int k0 = 0; k0 < 512; k0 += 32) {
        #pragma unroll
        for (int j = 0; j < 4; j++) {
            int k = ty + j * 8;
            t[k][tx] = w[(long long)(k0 + k) * 6144 + fbase + 3 * (c0 + tx)];
        }
        __syncthreads();
        #pragma unroll
        for (int j = 0; j < 4; j++) {
            int c = ty + j * 8;
            wT[(long long)(r0 + c) * 512 + k0 + tx] = t[tx][c];
        }
        __syncthreads();
    }
}

__global__ void tr_bias(const float* __restrict__ b, float* __restrict__ bT) {
    int r = blockIdx.x * 256 + threadIdx.x;   // 6144
    int sec = r >> 11, h = (r & 2047) >> 9, c = r & 511;
    bT[r] = b[h * 1536 + 3 * c + sec];
}

// w_out[f][c] -> woutT[c][f]
__global__ void tr_wout(const float* __restrict__ w, float* __restrict__ wT) {
    __shared__ float t[32][33];
    int f0 = blockIdx.x * 32, c0 = blockIdx.y * 32;
    int tx = threadIdx.x & 31, ty = threadIdx.x >> 5;
    #pragma unroll
    for (int j = 0; j < 4; j++)
        t[ty + j * 8][tx] = w[(long long)(f0 + ty + j * 8) * 512 + c0 + tx];
    __syncthreads();
    #pragma unroll
    for (int j = 0; j < 4; j++)
        wT[(long long)(c0 + ty + j * 8) * 2048 + f0 + tx] = t[tx][ty + j * 8];
}

// ---------------- softmax over rows of 512 ----------------
__global__ void softmax512(float* __restrict__ a) {
    float* row = a + (size_t)blockIdx.x * NC;
    int tid = threadIdx.x;
    float v0 = row[tid], v1 = row[tid + 256];
    float m = fmaxf(v0, v1);
    __shared__ float red[8];
    for (int o = 16; o; o >>= 1) m = fmaxf(m, __shfl_xor_sync(0xffffffffu, m, o));
    if ((tid & 31) == 0) red[tid >> 5] = m;
    __syncthreads();
    m = red[0];
    #pragma unroll
    for (int i = 1; i < 8; i++) m = fmaxf(m, red[i]);
    __syncthreads();
    float e0 = __expf(v0 - m), e1 = __expf(v1 - m);
    float s = e0 + e1;
    for (int o = 16; o; o >>= 1) s += __shfl_xor_sync(0xffffffffu, s, o);
    if ((tid & 31) == 0) red[tid >> 5] = s;
    __syncthreads();
    s = 0.f;
    #pragma unroll
    for (int i = 0; i < 8; i++) s += red[i];
    float inv = 1.0f / s;
    row[tid] = e0 * inv;
    row[tid + 256] = e1 * inv;
}

// ---------------- tf32 mma.sync GEMM ----------------
// C[m,n] = alpha*sum_k A[m,k]B[k,n] (+bias_m +bias_n +resid). A,B are k-CONTIGUOUS
// (Ask=Bsk=1). Row strides Asm (A m-stride), Bsn (B n-stride). CTA tile 128x128,
// BK=32, 8 warps of 32(M)x64(N). SMEM tile layout [row][36] floats (pad 4).

__device__ __forceinline__ float tf32r(float x) {
    asm("cvt.rna.tf32.f32 %0, %0;" : "+f"(x));
    return x;
}

#define TS (128 * 36)

__device__ __forceinline__ void ldg_tile(const float* __restrict__ src, long long Sr,
                                         int k0, int tid, float4* st) {
    const float* s = src + k0;
    #pragma unroll
    for (int it = 0; it < 4; it++) {
        int i = tid + it * 256;
        int r = i >> 3, q = i & 7;
        st[it] = *(const float4*)(s + (long long)r * Sr + q * 4);
    }
}

__device__ __forceinline__ void sts_tile(float* __restrict__ dst, int tid, const float4* st) {
    #pragma unroll
    for (int it = 0; it < 4; it++) {
        int i = tid + it * 256;
        int r = i >> 3, q = i & 7;
        float4 v = st[it];
        v.x = tf32r(v.x); v.y = tf32r(v.y); v.z = tf32r(v.z); v.w = tf32r(v.w);
        *(float4*)(dst + r * 36 + q * 4) = v;
    }
}

__device__ __forceinline__ void mma_block(float* acc, const float* __restrict__ As,
                                          const float* __restrict__ Bs,
                                          int wm, int wn, int lane) {
    int g = lane >> 2, qid = lane & 3;
    #pragma unroll
    for (int s = 0; s < 4; s++) {
        int k0 = s * 8 + qid;
        uint32_t a[2][4], b[8][2];
        #pragma unroll
        for (int mt = 0; mt < 2; mt++) {
            const float* ap = As + (wm + mt * 16 + g) * 36 + k0;
            a[mt][0] = __float_as_uint(ap[0]);
            a[mt][1] = __float_as_uint(ap[8 * 36]);
            a[mt][2] = __float_as_uint(ap[4]);
            a[mt][3] = __float_as_uint(ap[8 * 36 + 4]);
        }
        #pragma unroll
        for (int nt = 0; nt < 8; nt++) {
            const float* bp = Bs + (wn + nt * 8 + g) * 36 + k0;
            b[nt][0] = __float_as_uint(bp[0]);
            b[nt][1] = __float_as_uint(bp[4]);
        }
        #pragma unroll
        for (int mt = 0; mt < 2; mt++)
            #pragma unroll
            for (int nt = 0; nt < 8; nt++) {
                float* c = acc + (mt * 8 + nt) * 4;
                asm volatile(
                    "mma.sync.aligned.m16n8k8.row.col.f32.tf32.tf32.f32 "
                    "{%0,%1,%2,%3}, {%4,%5,%6,%7}, {%8,%9}, {%0,%1,%2,%3};"
                    : "+f"(c[0]), "+f"(c[1]), "+f"(c[2]), "+f"(c[3])
                    : "r"(a[mt][0]), "r"(a[mt][1]), "r"(a[mt][2]), "r"(a[mt][3]),
                      "r"(b[nt][0]), "r"(b[nt][1]));
            }
    }
}

__global__ void __launch_bounds__(256)
tgemm(const float* __restrict__ A, const float* __restrict__ B, float* __restrict__ C,
      int K, long long Asm, long long Bsn, long long Csm, long long Csn,
      int zInner, long long Abi, long long Abo, long long Bbi, long long Bbo,
      long long Cbi, long long Cbo, float alpha,
      const float* __restrict__ bias_m, const float* __restrict__ bias_n,
      const float* __restrict__ resid) {
    extern __shared__ float smf[];
    float* bufA0 = smf;
    float* bufB0 = smf + TS;
    float* bufA1 = smf + 2 * TS;
    float* bufB1 = smf + 3 * TS;

    int tid = threadIdx.x, lane = tid & 31, wid = tid >> 5;
    int wm = (wid & 3) * 32, wn = (wid >> 2) * 64;

    int z = blockIdx.z;
    int zi = z % zInner, zo = z / zInner;
    A += zi * Abi + zo * Abo;
    B += zi * Bbi + zo * Bbo;
    long long cbase = zi * Cbi + zo * Cbo;
    int m0 = blockIdx.y * 128;
    int n0 = blockIdx.x * 128;
    A += (long long)m0 * Asm;
    B += (long long)n0 * Bsn;

    float acc[64];
    #pragma unroll
    for (int i = 0; i < 64; i++) acc[i] = 0.f;

    float4 ra[4], rb[4];
    ldg_tile(A, Asm, 0, tid, ra);
    ldg_tile(B, Bsn, 0, tid, rb);
    sts_tile(bufA0, tid, ra);
    sts_tile(bufB0, tid, rb);
    __syncthreads();

    int KB = K >> 5;
    for (int kb = 0; kb < KB; kb++) {
        int cur = kb & 1;
        if (kb + 1 < KB) {
            ldg_tile(A, Asm, (kb + 1) * 32, tid, ra);
            ldg_tile(B, Bsn, (kb + 1) * 32, tid, rb);
        }
        mma_block(acc, cur ? bufA1 : bufA0, cur ? bufB1 : bufB0, wm, wn, lane);
        if (kb + 1 < KB) {
            sts_tile(cur ? bufA0 : bufA1, tid, ra);
            sts_tile(cur ? bufB0 : bufB1, tid, rb);
            __syncthreads();
        }
    }

    // epilogue
    int g = lane >> 2, qid = lane & 3;
    #pragma unroll
    for (int mt = 0; mt < 2; mt++) {
        int r = m0 + wm + mt * 16 + g;
        float bm0 = bias_m ? bias_m[r] : 0.f;
        float bm1 = bias_m ? bias_m[r + 8] : 0.f;
        #pragma unroll
        for (int nt = 0; nt < 8; nt++) {
            float* c = acc + (mt * 8 + nt) * 4;
            int n = n0 + wn + nt * 8 + qid * 2;
            float bn0 = 0.f, bn1 = 0.f;
            if (bias_n) { bn0 = bias_n[n]; bn1 = bias_n[n + 1]; }
            long long o0 = cbase + (long long)r * Csm + (long long)n * Csn;
            long long o1 = cbase + (long long)(r + 8) * Csm + (long long)n * Csn;
            float v00 = c[0] * alpha + bm0 + bn0;
            float v01 = c[1] * alpha + bm0 + bn1;
            float v10 = c[2] * alpha + bm1 + bn0;
            float v11 = c[3] * alpha + bm1 + bn1;
            if (Csn == 1) {
                if (resid) {
                    v00 += resid[o0]; v01 += resid[o0 + 1];
                    v10 += resid[o1]; v11 += resid[o1 + 1];
                }
                *(float2*)(C + o0) = make_float2(v00, v01);
                *(float2*)(C + o1) = make_float2(v10, v11);
            } else {
                C[o0] = v00; C[o0 + Csn] = v01;
                C[o1] = v10; C[o1 + Csn] = v11;
            }
        }
    }
}

#define GSMEM (4 * TS * 4)

extern "C" void kernel_launch(void* const* d_in, const int* in_sizes, int n_in,
                              void* d_out, int out_size) {
    const float* x        = (const float*)d_in[0];
    const float* gn_scale = (const float*)d_in[1];
    const float* gn_bias  = (const float*)d_in[2];
    const float* w_qkv    = (const float*)d_in[3];
    const float* b_qkv    = (const float*)d_in[4];
    const float* w_out    = (const float*)d_in[5];
    const float* b_out    = (const float*)d_in[6];
    float* out = (float*)d_out;

    float *h, *qkT, *v2, *attn, *av2, *wqkT, *woutT, *bqkT;
    cudaGetSymbolAddress((void**)&h,     g_h);
    cudaGetSymbolAddress((void**)&qkT,   g_qkT);
    cudaGetSymbolAddress((void**)&v2,    g_v2);
    cudaGetSymbolAddress((void**)&attn,  g_attn);
    cudaGetSymbolAddress((void**)&av2,   g_av2);
    cudaGetSymbolAddress((void**)&wqkT,  g_wqkT);
    cudaGetSymbolAddress((void**)&woutT, g_woutT);
    cudaGetSymbolAddress((void**)&bqkT,  g_bqkT);

    cudaFuncSetAttribute(tgemm, cudaFuncAttributeMaxDynamicSharedMemorySize, GSMEM);

    // prep: groupnorm + weight transposes
    gn_stats<<<NB * 32, 256>>>(x);
    gn_apply<<<(BT * NC) / 256, 256>>>(x, gn_scale, gn_bias);
    tr_wqkv<<<192, 256>>>(w_qkv, wqkT);
    tr_bias<<<24, 256>>>(b_qkv, bqkT);
    tr_wout<<<dim3(64, 16), 256>>>(w_out, woutT);

    // GEMM 2a: qkT[row=0..4095][bt] = wqkT(rows 0..4095) @ h^T
    // A[m][k=c]: Asm=512 ; B[k=c][n=bt]=h[n*512+c]: Bsn=512 ; C: Csm=8192, Csn=1
    tgemm<<<dim3(BT / 128, 4096 / 128, 1), 256, GSMEM>>>(
        wqkT, h, qkT, NC,
        512, 512, BT, 1,
        1, 0, 0, 0, 0, 0, 0,
        1.0f, bqkT, nullptr, nullptr);

    // GEMM 2b: v2[bt][f] (transposed C): m=f(2048), n=bt
    tgemm<<<dim3(BT / 128, NF / 128, 1), 256, GSMEM>>>(
        wqkT + 4096LL * 512, h, v2, NC,
        512, 512, 1, NF,
        1, 0, 0, 0, 0, 0, 0,
        1.0f, bqkT + 4096, nullptr, nullptr);

    // GEMM 3: logits[z][c][d] = (1/32) Q K^T ; z = b*4+h (zi=h, zo=b)
    // A[m=c][k=t] = qkT[(h*512+c)*8192 + b*1024 + t]
    // B[n=d][k=t] = qkT[(2048+h*512+d)*8192 + b*1024 + t]
    tgemm<<<dim3(NC / 128, NC / 128, 32), 256, GSMEM>>>(
        qkT, qkT + 2048LL * BT, attn, NT,
        BT, BT, NC, 1,
        NH,
        512LL * BT, NT, 512LL * BT, NT,
        (long long)NC * NC, 4LL * NC * NC,
        1.0f / 32.0f, nullptr, nullptr, nullptr);

    // softmax over d
    softmax512<<<32 * NC, 256>>>(attn);

    // GEMM 5: av2[bt][h*512+c] = P @ V ; m=c, n=t, transposed C
    // A[m=c][k=d] = attn[z][c][d]: Asm=512 ; B[n=t][k=d] = v2[(b*1024+t)*2048 + h*512+d]: Bsn=2048
    tgemm<<<dim3(NT / 128, NC / 128, 32), 256, GSMEM>>>(
        attn, v2, av2, NC,
        NC, NF, 1, NF,
        NH,
        (long long)NC * NC, 4LL * NC * NC,
        512, (long long)NT * NF,
        512, (long long)NT * NF,
        1.0f, nullptr, nullptr, nullptr);

    // GEMM 6: out[b][t][c] = av2[b*1024+t][f] @ woutT[c][f]^T + b_out + x
    tgemm<<<dim3(NC / 128, NT / 128, NB), 256, GSMEM>>>(
        av2, woutT, out, NF,
        NF, NF, NC, 1,
        1,
        0, (long long)NT * NF, 0, 0,
        0, (long long)NT * NC,
        1.0f, nullptr, b_out, x);
}

// round 4
// speedup vs baseline: 4.2273x; 1.0412x over previous
#include <cuda_runtime.h>
#include <cstdint>

#define NB 8
#define NT 1024
#define NC 512
#define NH 4
#define BT (NB*NT)          // 8192
#define NF 2048             // NH*NC

// ---------------- scratch (device globals) ----------------
__device__ float g_h[BT * NC];                     // groupnormed [bt][c-perm]
__device__ float g_qkT[(long long)2 * NF * BT];    // [feat row][bt-perm] rows 0..2047=Q, 2048..4095=K
__device__ float g_v2[(long long)BT * NF];         // [bt][f-perm]
__device__ float g_attn[32 * NC * NC];             // [b*4+h][c][d-perm]
__device__ float g_av2[(long long)BT * NF];        // [bt][f-perm]
__device__ float g_wqkT[6144 * NC];                // [row][c-perm]
__device__ float g_woutT[NC * NF];                 // [c][f-perm]
__device__ float g_bqkT[6144];
__device__ float g_mean[NB * 32];
__device__ float g_rstd[NB * 32];

__device__ __forceinline__ int perm32(int k) { return ((k & 3) << 3) | (k >> 2); }

__device__ __forceinline__ float tf32r(float x) {
    asm("cvt.rna.tf32.f32 %0, %0;" : "+f"(x));
    return x;
}

__device__ __forceinline__ uint32_t smem_u32(const void* p) {
    uint32_t a;
    asm("{ .reg .u64 t; cvta.to.shared.u64 t, %1; cvt.u32.u64 %0, t; }" : "=r"(a) : "l"(p));
    return a;
}

#define CPASYNC16(dst, src) \
    asm volatile("cp.async.cg.shared.global [%0], [%1], 16;" :: "r"(dst), "l"(src))
#define CP_COMMIT() asm volatile("cp.async.commit_group;" ::: "memory")
#define CP_WAIT1()  asm volatile("cp.async.wait_group 1;" ::: "memory")

// ---------------- GroupNorm ----------------
__global__ void gn_stats(const float* __restrict__ x) {
    int bg = blockIdx.x;
    int b = bg >> 5, g = bg & 31;
    const float* base = x + (size_t)b * (NT * NC) + g * 16;
    float s = 0.f, ss = 0.f;
    for (int idx = threadIdx.x; idx < NT * 16; idx += 256) {
        float v = base[(idx >> 4) * NC + (idx & 15)];
        s += v; ss += v * v;
    }
    for (int o = 16; o; o >>= 1) {
        s  += __shfl_xor_sync(0xffffffffu, s,  o);
        ss += __shfl_xor_sync(0xffffffffu, ss, o);
    }
    __shared__ float sa[8], sb[8];
    int wid = threadIdx.x >> 5;
    if ((threadIdx.x & 31) == 0) { sa[wid] = s; sb[wid] = ss; }
    __syncthreads();
    if (threadIdx.x == 0) {
        float S = 0.f, SS = 0.f;
        #pragma unroll
        for (int i = 0; i < 8; i++) { S += sa[i]; SS += sb[i]; }
        float inv = 1.0f / (NT * 16);
        float mean = S * inv;
        float var  = SS * inv - mean * mean;
        g_mean[bg] = mean;
        g_rstd[bg] = rsqrtf(var + 1e-5f);
    }
}

__global__ void gn_apply(const float* __restrict__ x,
                         const float* __restrict__ scale,
                         const float* __restrict__ bias) {
    int idx = blockIdx.x * 256 + threadIdx.x;
    if (idx >= BT * NC) return;
    int c = idx & (NC - 1);
    int b = idx >> 19;
    int bg = b * 32 + (c >> 4);
    float v = (x[idx] - g_mean[bg]) * g_rstd[bg] * scale[c] + bias[c];
    g_h[idx - (c & 31) + perm32(c & 31)] = tf32r(v);
}

// ---------------- weight transposes (write k-permuted + tf32-rounded) ----------------
__global__ void tr_wqkv(const float* __restrict__ w, float* __restrict__ wT) {
    __shared__ float t[32][33];
    int blk = blockIdx.x;             // 0..191
    int sec = blk >> 6;
    int within = blk & 63;
    int h = within >> 4, ct = within & 15;
    int c0 = ct * 32;
    int fbase = h * 1536 + sec;
    int r0 = sec * 2048 + h * 512 + c0;
    int tx = threadIdx.x & 31, ty = threadIdx.x >> 5;
    for (int k0 = 0; k0 < 512; k0 += 32) {
        #pragma unroll
        for (int j = 0; j < 4; j++) {
            int k = ty + j * 8;
            t[k][tx] = w[(long long)(k0 + k) * 6144 + fbase + 3 * (c0 + tx)];
        }
        __syncthreads();
        #pragma unroll
        for (int j = 0; j < 4; j++) {
            int cc = ty + j * 8;
            wT[(long long)(r0 + cc) * 512 + k0 + perm32(tx)] = tf32r(t[tx][cc]);
        }
        __syncthreads();
    }
}

__global__ void tr_bias(const float* __restrict__ b, float* __restrict__ bT) {
    int r = blockIdx.x * 256 + threadIdx.x;
    int sec = r >> 11, h = (r & 2047) >> 9, c = r & 511;
    bT[r] = b[h * 1536 + 3 * c + sec];
}

__global__ void tr_wout(const float* __restrict__ w, float* __restrict__ wT) {
    __shared__ float t[32][33];
    int f0 = blockIdx.x * 32, c0 = blockIdx.y * 32;
    int tx = threadIdx.x & 31, ty = threadIdx.x >> 5;
    #pragma unroll
    for (int j = 0; j < 4; j++)
        t[ty + j * 8][tx] = w[(long long)(f0 + ty + j * 8) * 512 + c0 + tx];
    __syncthreads();
    #pragma unroll
    for (int j = 0; j < 4; j++)
        wT[(long long)(c0 + ty + j * 8) * 2048 + f0 + perm32(tx)] = tf32r(t[tx][ty + j * 8]);
}

// ---------------- softmax over rows of 512 (perm-invariant; rounds output) ----------------
__global__ void softmax512(float* __restrict__ a) {
    float* row = a + (size_t)blockIdx.x * NC;
    int tid = threadIdx.x;
    float v0 = row[tid], v1 = row[tid + 256];
    float m = fmaxf(v0, v1);
    __shared__ float red[8];
    for (int o = 16; o; o >>= 1) m = fmaxf(m, __shfl_xor_sync(0xffffffffu, m, o));
    if ((tid & 31) == 0) red[tid >> 5] = m;
    __syncthreads();
    m = red[0];
    #pragma unroll
    for (int i = 1; i < 8; i++) m = fmaxf(m, red[i]);
    __syncthreads();
    float e0 = __expf(v0 - m), e1 = __expf(v1 - m);
    float s = e0 + e1;
    for (int o = 16; o; o >>= 1) s += __shfl_xor_sync(0xffffffffu, s, o);
    if ((tid & 31) == 0) red[tid >> 5] = s;
    __syncthreads();
    s = 0.f;
    #pragma unroll
    for (int i = 0; i < 8; i++) s += red[i];
    float inv = 1.0f / s;
    row[tid] = tf32r(e0 * inv);
    row[tid + 256] = tf32r(e1 * inv);
}

// ---------------- tf32 mma.sync GEMM, fragment-major smem, cp.async 3-stage ----------
// Global A,B are k-contiguous AND k-permuted within 32-blocks.
// CTA tile 128x128, BK=32. 8 warps as 2(M)x4(N): warp tile 64x32.
// Smem row = 36 floats (pad 4); 16B chunk p stored at p ^ ((row&3)<<1).

#define TROW 36
#define TILEF (128 * TROW)      // 4608 floats per operand tile
#define STAGEF (2 * TILEF)      // 9216
#define GSMEM (3 * STAGEF * 4)  // 110592 bytes

#define MMA_OP(d, a0, a1, a2, a3, b0, b1) \
    asm volatile("mma.sync.aligned.m16n8k8.row.col.f32.tf32.tf32.f32 " \
        "{%0,%1,%2,%3}, {%4,%5,%6,%7}, {%8,%9}, {%0,%1,%2,%3};" \
        : "+f"((d)[0]), "+f"((d)[1]), "+f"((d)[2]), "+f"((d)[3]) \
        : "r"(__float_as_uint(a0)), "r"(__float_as_uint(a1)), \
          "r"(__float_as_uint(a2)), "r"(__float_as_uint(a3)), \
          "r"(__float_as_uint(b0)), "r"(__float_as_uint(b1)))

__global__ void __launch_bounds__(256, 2)
tgemm(const float* __restrict__ A, const float* __restrict__ B, float* __restrict__ C,
      int K, long long Asm, long long Bsn, long long Csm, long long Csn,
      int zInner, long long Abi, long long Abo, long long Bbi, long long Bbo,
      long long Cbi, long long Cbo, float alpha,
      const float* __restrict__ bias_m, const float* __restrict__ bias_n,
      const float* __restrict__ resid, int permN, int permM) {
    extern __shared__ float smf[];
    int tid = threadIdx.x, lane = tid & 31, wid = tid >> 5;
    int g = lane >> 2, qid = lane & 3;
    int wm = (wid & 1) * 64, wn = (wid >> 1) * 32;

    int z = blockIdx.z;
    int zi = z % zInner, zo = z / zInner;
    A += zi * Abi + zo * Abo;
    B += zi * Bbi + zo * Bbo;
    long long cbase = zi * Cbi + zo * Cbo;
    int m0 = blockIdx.y * 128;
    int n0 = blockIdx.x * 128;
    A += (long long)m0 * Asm;
    B += (long long)n0 * Bsn;

    // cp.async source/dest bases for this thread
    int row0 = tid >> 3, p = tid & 7;
    int pp0 = p ^ ((row0 & 3) << 1);
    const float* srcA = A + (long long)row0 * Asm + p * 4;
    const float* srcB = B + (long long)row0 * Bsn + p * 4;
    uint32_t sb = smem_u32(smf);
    uint32_t dA0 = sb + (uint32_t)(row0 * TROW + pp0 * 4) * 4;
    uint32_t dB0 = dA0 + TILEF * 4;

    float acc[4][4][4];
    #pragma unroll
    for (int i = 0; i < 4; i++)
        #pragma unroll
        for (int j = 0; j < 4; j++)
            #pragma unroll
            for (int q = 0; q < 4; q++) acc[i][j][q] = 0.f;

    int KB = K >> 5;

    // prologue: stages 0,1
    #pragma unroll
    for (int s = 0; s < 2; s++) {
        uint32_t so = (uint32_t)(s * STAGEF) * 4;
        #pragma unroll
        for (int t = 0; t < 4; t++) {
            CPASYNC16(dA0 + so + t * (32 * TROW * 4), srcA + s * 32 + (long long)(32 * t) * Asm);
            CPASYNC16(dB0 + so + t * (32 * TROW * 4), srcB + s * 32 + (long long)(32 * t) * Bsn);
        }
        CP_COMMIT();
    }

    int xc = (g & 3) << 1;
    int st = 0;
    for (int kb = 0; kb < KB; kb++) {
        CP_WAIT1();
        __syncthreads();
        // issue kb+2
        if (kb + 2 < KB) {
            int s2 = st + 2; if (s2 >= 3) s2 -= 3;
            uint32_t so = (uint32_t)(s2 * STAGEF) * 4;
            #pragma unroll
            for (int t = 0; t < 4; t++) {
                CPASYNC16(dA0 + so + t * (32 * TROW * 4), srcA + (kb + 2) * 32 + (long long)(32 * t) * Asm);
                CPASYNC16(dB0 + so + t * (32 * TROW * 4), srcB + (kb + 2) * 32 + (long long)(32 * t) * Bsn);
            }
        }
        CP_COMMIT();

        const float* bufA = smf + st * STAGEF;
        const float* bufB = bufA + TILEF;

        #pragma unroll
        for (int h = 0; h < 2; h++) {
            int pph = (2 * qid + h) ^ xc;
            float4 fb[4];
            #pragma unroll
            for (int nt = 0; nt < 4; nt++)
                fb[nt] = *(const float4*)(bufB + (wn + 8 * nt + g) * TROW + pph * 4);
            #pragma unroll
            for (int mp = 0; mp < 2; mp++) {
                float4 fa[4];
                #pragma unroll
                for (int u = 0; u < 4; u++)
                    fa[u] = *(const float4*)(bufA + (wm + 32 * mp + 8 * u + g) * TROW + pph * 4);
                #pragma unroll
                for (int mi = 0; mi < 2; mi++) {
                    int mt = 2 * mp + mi;
                    // s2 = 0 -> (x,y), s2 = 1 -> (z,w)
                    #pragma unroll
                    for (int nt = 0; nt < 4; nt++)
                        MMA_OP(acc[mt][nt], fa[2 * mi].x, fa[2 * mi + 1].x,
                               fa[2 * mi].y, fa[2 * mi + 1].y, fb[nt].x, fb[nt].y);
                    #pragma unroll
                    for (int nt = 0; nt < 4; nt++)
                        MMA_OP(acc[mt][nt], fa[2 * mi].z, fa[2 * mi + 1].z,
                               fa[2 * mi].w, fa[2 * mi + 1].w, fb[nt].z, fb[nt].w);
                }
            }
        }
        st++; if (st == 3) st = 0;
    }

    // ---------------- epilogue ----------------
    #pragma unroll
    for (int mt = 0; mt < 4; mt++) {
        int r = m0 + wm + 16 * mt + g;
        float bm0 = bias_m ? bias_m[r] : 0.f;
        float bm1 = bias_m ? bias_m[r + 8] : 0.f;
        #pragma unroll
        for (int nt = 0; nt < 4; nt++) {
            float* c = acc[mt][nt];
            int n = n0 + wn + 8 * nt + qid * 2;
            float bn0 = 0.f, bn1 = 0.f;
            if (bias_n) { bn0 = bias_n[n]; bn1 = bias_n[n + 1]; }
            float v00 = c[0] * alpha + bm0 + bn0;
            float v01 = c[1] * alpha + bm0 + bn1;
            float v10 = c[2] * alpha + bm1 + bn0;
            float v11 = c[3] * alpha + bm1 + bn1;
            if (permN) {
                int pn = (n & ~31) + perm32(n & 31);
                long long o0 = cbase + (long long)r * Csm + pn;
                long long o1 = cbase + (long long)(r + 8) * Csm + pn;
                C[o0] = tf32r(v00); C[o0 + 8] = tf32r(v01);
                C[o1] = tf32r(v10); C[o1 + 8] = tf32r(v11);
            } else if (permM) {
                int pr0 = (r & ~31) + perm32(r & 31);
                long long o0 = cbase + pr0 + (long long)n * Csn;
                long long o1 = o0 + 2;   // r+8 -> same q, j+2
                C[o0] = tf32r(v00); C[o0 + Csn] = tf32r(v01);
                C[o1] = tf32r(v10); C[o1 + Csn] = tf32r(v11);
            } else {
                long long o0 = cbase + (long long)r * Csm + n;
                long long o1 = cbase + (long long)(r + 8) * Csm + n;
                if (resid) {
                    v00 += resid[o0]; v01 += resid[o0 + 1];
                    v10 += resid[o1]; v11 += resid[o1 + 1];
                }
                *(float2*)(C + o0) = make_float2(v00, v01);
                *(float2*)(C + o1) = make_float2(v10, v11);
            }
        }
    }
}

extern "C" void kernel_launch(void* const* d_in, const int* in_sizes, int n_in,
                              void* d_out, int out_size) {
    const float* x        = (const float*)d_in[0];
    const float* gn_scale = (const float*)d_in[1];
    const float* gn_bias  = (const float*)d_in[2];
    const float* w_qkv    = (const float*)d_in[3];
    const float* b_qkv    = (const float*)d_in[4];
    const float* w_out    = (const float*)d_in[5];
    const float* b_out    = (const float*)d_in[6];
    float* out = (float*)d_out;

    float *h, *qkT, *v2, *attn, *av2, *wqkT, *woutT, *bqkT;
    cudaGetSymbolAddress((void**)&h,     g_h);
    cudaGetSymbolAddress((void**)&qkT,   g_qkT);
    cudaGetSymbolAddress((void**)&v2,    g_v2);
    cudaGetSymbolAddress((void**)&attn,  g_attn);
    cudaGetSymbolAddress((void**)&av2,   g_av2);
    cudaGetSymbolAddress((void**)&wqkT,  g_wqkT);
    cudaGetSymbolAddress((void**)&woutT, g_woutT);
    cudaGetSymbolAddress((void**)&bqkT,  g_bqkT);

    cudaFuncSetAttribute(tgemm, cudaFuncAttributeMaxDynamicSharedMemorySize, GSMEM);

    gn_stats<<<NB * 32, 256>>>(x);
    gn_apply<<<(BT * NC) / 256, 256>>>(x, gn_scale, gn_bias);
    tr_wqkv<<<192, 256>>>(w_qkv, wqkT);
    tr_bias<<<24, 256>>>(b_qkv, bqkT);
    tr_wout<<<dim3(64, 16), 256>>>(w_out, woutT);

    // GEMM 2a: qkT[feat 0..4095][bt-perm]
    tgemm<<<dim3(BT / 128, 4096 / 128, 1), 256, GSMEM>>>(
        wqkT, h, qkT, NC,
        512, 512, BT, 1,
        1, 0, 0, 0, 0, 0, 0,
        1.0f, bqkT, nullptr, nullptr, 1, 0);

    // GEMM 2b: v2[bt][f-perm] (C transposed: m=f contiguous-permuted)
    tgemm<<<dim3(BT / 128, NF / 128, 1), 256, GSMEM>>>(
        wqkT + 4096LL * 512, h, v2, NC,
        512, 512, 1, NF,
        1, 0, 0, 0, 0, 0, 0,
        1.0f, bqkT + 4096, nullptr, nullptr, 0, 1);

    // GEMM 3: logits = (1/32) Q K^T ; z = b*4+h
    tgemm<<<dim3(NC / 128, NC / 128, 32), 256, GSMEM>>>(
        qkT, qkT + 2048LL * BT, attn, NT,
        BT, BT, NC, 1,
        NH,
        512LL * BT, NT, 512LL * BT, NT,
        (long long)NC * NC, 4LL * NC * NC,
        1.0f / 32.0f, nullptr, nullptr, nullptr, 1, 0);

    softmax512<<<32 * NC, 256>>>(attn);

    // GEMM 5: av2[bt][f-perm] = P @ V (C transposed: m=c)
    tgemm<<<dim3(NT / 128, NC / 128, 32), 256, GSMEM>>>(
        attn, v2, av2, NC,
        NC, NF, 1, NF,
        NH,
        (long long)NC * NC, 4LL * NC * NC,
        512, (long long)NT * NF,
        512, (long long)NT * NF,
        1.0f, nullptr, nullptr, nullptr, 0, 1);

    // GEMM 6: out = av2 @ woutT^T + b_out + x  (plain output)
    tgemm<<<dim3(NC / 128, NT / 128, NB), 256, GSMEM>>>(
        av2, woutT, out, NF,
        NF, NF, NC, 1,
        1,
        0, (long long)NT * NF, 0, 0,
        0, (long long)NT * NC,
        1.0f, nullptr, b_out, x, 0, 0);
}

// round 5
// speedup vs baseline: 10.4536x; 2.4729x over previous
#include <cuda_runtime.h>
#include <cuda_fp16.h>
#include <cstdint>

#define NB 8
#define NT 1024
#define NC 512
#define NH 4
#define BT (NB*NT)          // 8192
#define NF 2048             // NH*NC

// ---------------- scratch (device globals) ----------------
__device__ __half g_h[BT * NC];                     // [bt][c]
__device__ __half g_qkT[(long long)4096 * BT];      // rows 0..2047 Q(h*512+c), 2048..4095 K ; [row][bt]
__device__ __half g_v2[(long long)BT * NF];         // [bt][h*512+d]
__device__ float  g_attn[32 * NC * NC];             // [b*4+h][c][d]  (fp32 logits)
__device__ __half g_attnh[32 * NC * NC];            // softmaxed, fp16
__device__ __half g_av2[(long long)BT * NF];        // [bt][h*512+c]
__device__ __half g_wqkT[6144 * NC];                // [row][c] row: sec*2048 + h*512 + c  (sec2 = V weights)
__device__ __half g_woutT[NC * NF];                 // [c][f]
__device__ float  g_bqkT[6144];
__device__ float  g_mean[NB * 32];
__device__ float  g_rstd[NB * 32];

__device__ __forceinline__ uint32_t smem_u32(const void* p) {
    uint32_t a;
    asm("{ .reg .u64 t; cvta.to.shared.u64 t, %1; cvt.u32.u64 %0, t; }" : "=r"(a) : "l"(p));
    return a;
}
#define SWZ(o) ((o) ^ (((o) >> 3) & 0x70))

#define CPASYNC16(dst, src) \
    asm volatile("cp.async.cg.shared.global [%0], [%1], 16;" :: "r"(dst), "l"(src))
#define CP_COMMIT() asm volatile("cp.async.commit_group;" ::: "memory")
#define CP_WAIT1()  asm volatile("cp.async.wait_group 1;" ::: "memory")

#define LDSM4(r0, r1, r2, r3, addr) \
    asm volatile("ldmatrix.sync.aligned.m8n8.x4.shared.b16 {%0,%1,%2,%3}, [%4];" \
        : "=r"(r0), "=r"(r1), "=r"(r2), "=r"(r3) : "r"(addr))

#define HMMA16(d, a0, a1, a2, a3, b0, b1) \
    asm volatile("mma.sync.aligned.m16n8k16.row.col.f32.f16.f16.f32 " \
        "{%0,%1,%2,%3}, {%4,%5,%6,%7}, {%8,%9}, {%0,%1,%2,%3};" \
        : "+f"((d)[0]), "+f"((d)[1]), "+f"((d)[2]), "+f"((d)[3]) \
        : "r"(a0), "r"(a1), "r"(a2), "r"(a3), "r"(b0), "r"(b1))

// ---------------- GroupNorm ----------------
__global__ void gn_stats(const float* __restrict__ x) {
    int bg = blockIdx.x;
    int b = bg >> 5, g = bg & 31;
    const float* base = x + (size_t)b * (NT * NC) + g * 16;
    float s = 0.f, ss = 0.f;
    for (int idx = threadIdx.x; idx < NT * 16; idx += 256) {
        float v = base[(idx >> 4) * NC + (idx & 15)];
        s += v; ss += v * v;
    }
    for (int o = 16; o; o >>= 1) {
        s  += __shfl_xor_sync(0xffffffffu, s,  o);
        ss += __shfl_xor_sync(0xffffffffu, ss, o);
    }
    __shared__ float sa[8], sb[8];
    int wid = threadIdx.x >> 5;
    if ((threadIdx.x & 31) == 0) { sa[wid] = s; sb[wid] = ss; }
    __syncthreads();
    if (threadIdx.x == 0) {
        float S = 0.f, SS = 0.f;
        #pragma unroll
        for (int i = 0; i < 8; i++) { S += sa[i]; SS += sb[i]; }
        float inv = 1.0f / (NT * 16);
        float mean = S * inv;
        float var  = SS * inv - mean * mean;
        g_mean[bg] = mean;
        g_rstd[bg] = rsqrtf(var + 1e-5f);
    }
}

__global__ void gn_apply(const float* __restrict__ x,
                         const float* __restrict__ scale,
                         const float* __restrict__ bias) {
    int idx = blockIdx.x * 256 + threadIdx.x;
    if (idx >= BT * NC) return;
    int c = idx & (NC - 1);
    int b = idx >> 19;
    int bg = b * 32 + (c >> 4);
    float v = (x[idx] - g_mean[bg]) * g_rstd[bg] * scale[c] + bias[c];
    g_h[idx] = __float2half(v);
}

// ---------------- weight transposes ----------------
__global__ void tr_wqkv(const float* __restrict__ w, __half* __restrict__ wT) {
    __shared__ float t[32][33];
    int blk = blockIdx.x;             // 0..191
    int sec = blk >> 6;
    int within = blk & 63;
    int h = within >> 4, ct = within & 15;
    int c0 = ct * 32;
    int fbase = h * 1536 + sec;
    int r0 = sec * 2048 + h * 512 + c0;
    int tx = threadIdx.x & 31, ty = threadIdx.x >> 5;
    for (int k0 = 0; k0 < 512; k0 += 32) {
        #pragma unroll
        for (int j = 0; j < 4; j++) {
            int k = ty + j * 8;
            t[k][tx] = w[(long long)(k0 + k) * 6144 + fbase + 3 * (c0 + tx)];
        }
        __syncthreads();
        #pragma unroll
        for (int j = 0; j < 4; j++) {
            int cc = ty + j * 8;
            wT[(long long)(r0 + cc) * 512 + k0 + tx] = __float2half(t[tx][cc]);
        }
        __syncthreads();
    }
}

__global__ void tr_bias(const float* __restrict__ b, float* __restrict__ bT) {
    int r = blockIdx.x * 256 + threadIdx.x;
    int sec = r >> 11, h = (r & 2047) >> 9, c = r & 511;
    bT[r] = b[h * 1536 + 3 * c + sec];
}

__global__ void tr_wout(const float* __restrict__ w, __half* __restrict__ wT) {
    __shared__ float t[32][33];
    int f0 = blockIdx.x * 32, c0 = blockIdx.y * 32;
    int tx = threadIdx.x & 31, ty = threadIdx.x >> 5;
    #pragma unroll
    for (int j = 0; j < 4; j++)
        t[ty + j * 8][tx] = w[(long long)(f0 + ty + j * 8) * 512 + c0 + tx];
    __syncthreads();
    #pragma unroll
    for (int j = 0; j < 4; j++)
        wT[(long long)(c0 + ty + j * 8) * 2048 + f0 + tx] = __float2half(t[tx][ty + j * 8]);
}

// ---------------- softmax: fp32 in, fp16 out ----------------
__global__ void softmax512(const float* __restrict__ a, __half* __restrict__ o) {
    const float* row = a + (size_t)blockIdx.x * NC;
    __half* orow = o + (size_t)blockIdx.x * NC;
    int tid = threadIdx.x;
    float v0 = row[tid], v1 = row[tid + 256];
    float m = fmaxf(v0, v1);
    __shared__ float red[8];
    for (int off = 16; off; off >>= 1) m = fmaxf(m, __shfl_xor_sync(0xffffffffu, m, off));
    if ((tid & 31) == 0) red[tid >> 5] = m;
    __syncthreads();
    m = red[0];
    #pragma unroll
    for (int i = 1; i < 8; i++) m = fmaxf(m, red[i]);
    __syncthreads();
    float e0 = __expf(v0 - m), e1 = __expf(v1 - m);
    float s = e0 + e1;
    for (int off = 16; off; off >>= 1) s += __shfl_xor_sync(0xffffffffu, s, off);
    if ((tid & 31) == 0) red[tid >> 5] = s;
    __syncthreads();
    s = 0.f;
    #pragma unroll
    for (int i = 0; i < 8; i++) s += red[i];
    float inv = 1.0f / s;
    orow[tid] = __float2half(e0 * inv);
    orow[tid + 256] = __float2half(e1 * inv);
}

// ---------------- fp16 mma.sync GEMM, SW128 + ldmatrix + cp.async 3-stage --------
// C[m,n] = alpha*sum_k A[m,k]B[n,k] (+bias_m +bias_n +resid)  A,B k-contiguous fp16.
// CTA tile 128x128, BK=64. 8 warps 2(M)x4(N): warp tile 64x32.
// smem stage = A(128x64h =16KB) + B(16KB) = 32KB, 3 stages.

#define STAGEB 32768
#define GSMEM (3 * STAGEB)

__global__ void __launch_bounds__(256, 2)
hgemm(const __half* __restrict__ A, const __half* __restrict__ B, void* __restrict__ Cv,
      int K, long long Asm, long long Bsn, long long Csm,
      int zInner, long long Abi, long long Abo, long long Bbi, long long Bbo,
      long long Cbi, long long Cbo, float alpha,
      const float* __restrict__ bias_m, const float* __restrict__ bias_n,
      const float* __restrict__ resid, int c16) {
    extern __shared__ char smem[];
    uint32_t sbase = smem_u32(smem);
    int tid = threadIdx.x, lane = tid & 31, wid = tid >> 5;
    int g = lane >> 2, qid = lane & 3;
    int wm = (wid & 1) * 64, wn = (wid >> 1) * 32;

    int z = blockIdx.z;
    int zi = z % zInner, zo = z / zInner;
    A += zi * Abi + zo * Abo;
    B += zi * Bbi + zo * Bbo;
    long long cbase = zi * Cbi + zo * Cbo;
    int m0 = blockIdx.y * 128;
    int n0 = blockIdx.x * 128;
    A += (long long)m0 * Asm;
    B += (long long)n0 * Bsn;

    // cp.async mapping: 1024 16B-chunks per 16KB tile; 4 per thread per tile
    int row0 = tid >> 3, q0 = tid & 7;           // chunk (row, q) for t=0
    const __half* srcA = A + (long long)row0 * Asm + q0 * 8;
    const __half* srcB = B + (long long)row0 * Bsn + q0 * 8;
    uint32_t dstA = sbase + SWZ((uint32_t)(row0 * 128 + q0 * 16));
    // rows advance by 32 per t; 32*128 bytes doesn't touch swizzle bits' low part
    // but SWZ depends on row bits 0..2 only (bits 7..9 of offset); +32 rows keeps them.

    float acc[4][4][4];
    #pragma unroll
    for (int i = 0; i < 4; i++)
        #pragma unroll
        for (int j = 0; j < 4; j++)
            #pragma unroll
            for (int qq = 0; qq < 4; qq++) acc[i][j][qq] = 0.f;

    int KB = K >> 6;

    #pragma unroll
    for (int s = 0; s < 2; s++) {
        uint32_t so = s * STAGEB;
        #pragma unroll
        for (int t = 0; t < 4; t++) {
            CPASYNC16(dstA + so + t * (32 * 128),         srcA + s * 64 + (long long)(32 * t) * Asm);
            CPASYNC16(dstA + so + 16384 + t * (32 * 128), srcB + s * 64 + (long long)(32 * t) * Bsn);
        }
        CP_COMMIT();
    }

    // ldmatrix per-lane base offsets (byte, pre-swizzle)
    uint32_t baseA = (uint32_t)((wm + (lane & 15)) * 128 + (lane >> 4) * 16);
    uint32_t baseB = (uint32_t)((wn + (lane & 7) + ((lane >> 4) & 1) * 8) * 128 + ((lane >> 3) & 1) * 16);

    int st = 0;
    for (int kb = 0; kb < KB; kb++) {
        CP_WAIT1();
        __syncthreads();
        if (kb + 2 < KB) {
            int s2 = st + 2; if (s2 >= 3) s2 -= 3;
            uint32_t so = (uint32_t)s2 * STAGEB;
            #pragma unroll
            for (int t = 0; t < 4; t++) {
                CPASYNC16(dstA + so + t * (32 * 128),         srcA + (kb + 2) * 64 + (long long)(32 * t) * Asm);
                CPASYNC16(dstA + so + 16384 + t * (32 * 128), srcB + (kb + 2) * 64 + (long long)(32 * t) * Bsn);
            }
        }
        CP_COMMIT();

        uint32_t sA = sbase + st * STAGEB;
        uint32_t sB = sA + 16384;

        #pragma unroll
        for (int ks = 0; ks < 4; ks++) {
            uint32_t a[4][4], bf[2][4];
            #pragma unroll
            for (int mt = 0; mt < 4; mt++)
                LDSM4(a[mt][0], a[mt][1], a[mt][2], a[mt][3],
                      sA + SWZ(baseA + mt * 2048 + ks * 32));
            #pragma unroll
            for (int ntp = 0; ntp < 2; ntp++)
                LDSM4(bf[ntp][0], bf[ntp][1], bf[ntp][2], bf[ntp][3],
                      sB + SWZ(baseB + ntp * 2048 + ks * 32));
            #pragma unroll
            for (int mt = 0; mt < 4; mt++)
                #pragma unroll
                for (int nt = 0; nt < 4; nt++) {
                    uint32_t b0 = bf[nt >> 1][(nt & 1) * 2];
                    uint32_t b1 = bf[nt >> 1][(nt & 1) * 2 + 1];
                    HMMA16(acc[mt][nt], a[mt][0], a[mt][1], a[mt][2], a[mt][3], b0, b1);
                }
        }
        st++; if (st == 3) st = 0;
    }

    // ---------------- epilogue ----------------
    #pragma unroll
    for (int mt = 0; mt < 4; mt++) {
        int r = m0 + wm + 16 * mt + g;
        float bm0 = bias_m ? bias_m[r] : 0.f;
        float bm1 = bias_m ? bias_m[r + 8] : 0.f;
        #pragma unroll
        for (int nt = 0; nt < 4; nt++) {
            float* c = acc[mt][nt];
            int n = n0 + wn + 8 * nt + qid * 2;
            float bn0 = 0.f, bn1 = 0.f;
            if (bias_n) { bn0 = bias_n[n]; bn1 = bias_n[n + 1]; }
            float v00 = c[0] * alpha + bm0 + bn0;
            float v01 = c[1] * alpha + bm0 + bn1;
            float v10 = c[2] * alpha + bm1 + bn0;
            float v11 = c[3] * alpha + bm1 + bn1;
            long long o0 = cbase + (long long)r * Csm + n;
            long long o1 = cbase + (long long)(r + 8) * Csm + n;
            if (c16) {
                *(__half2*)((__half*)Cv + o0) = __floats2half2_rn(v00, v01);
                *(__half2*)((__half*)Cv + o1) = __floats2half2_rn(v10, v11);
            } else {
                float* C = (float*)Cv;
                if (resid) {
                    v00 += resid[o0]; v01 += resid[o0 + 1];
                    v10 += resid[o1]; v11 += resid[o1 + 1];
                }
                *(float2*)(C + o0) = make_float2(v00, v01);
                *(float2*)(C + o1) = make_float2(v10, v11);
            }
        }
    }
}

extern "C" void kernel_launch(void* const* d_in, const int* in_sizes, int n_in,
                              void* d_out, int out_size) {
    const float* x        = (const float*)d_in[0];
    const float* gn_scale = (const float*)d_in[1];
    const float* gn_bias  = (const float*)d_in[2];
    const float* w_qkv    = (const float*)d_in[3];
    const float* b_qkv    = (const float*)d_in[4];
    const float* w_out    = (const float*)d_in[5];
    const float* b_out    = (const float*)d_in[6];
    float* out = (float*)d_out;

    __half *h, *qkT, *v2, *attnh, *av2, *wqkT, *woutT;
    float *attn, *bqkT;
    cudaGetSymbolAddress((void**)&h,     g_h);
    cudaGetSymbolAddress((void**)&qkT,   g_qkT);
    cudaGetSymbolAddress((void**)&v2,    g_v2);
    cudaGetSymbolAddress((void**)&attn,  g_attn);
    cudaGetSymbolAddress((void**)&attnh, g_attnh);
    cudaGetSymbolAddress((void**)&av2,   g_av2);
    cudaGetSymbolAddress((void**)&wqkT,  g_wqkT);
    cudaGetSymbolAddress((void**)&woutT, g_woutT);
    cudaGetSymbolAddress((void**)&bqkT,  g_bqkT);

    cudaFuncSetAttribute(hgemm, cudaFuncAttributeMaxDynamicSharedMemorySize, GSMEM);

    gn_stats<<<NB * 32, 256>>>(x);
    gn_apply<<<(BT * NC) / 256, 256>>>(x, gn_scale, gn_bias);
    tr_wqkv<<<192, 256>>>(w_qkv, wqkT);
    tr_bias<<<24, 256>>>(b_qkv, bqkT);
    tr_wout<<<dim3(64, 16), 256>>>(w_out, woutT);

    // GEMM 2a: qkT[feat 0..4095][bt]  (m=feat, n=bt)
    hgemm<<<dim3(BT / 128, 4096 / 128, 1), 256, GSMEM>>>(
        wqkT, h, qkT, NC,
        512, 512, BT,
        1, 0, 0, 0, 0, 0, 0,
        1.0f, bqkT, nullptr, nullptr, 1);

    // GEMM 2b: v2[bt][f]  (m=bt, n=f; B = V-weights rows of wqkT)
    hgemm<<<dim3(NF / 128, BT / 128, 1), 256, GSMEM>>>(
        h, wqkT + 4096LL * 512, v2, NC,
        512, 512, NF,
        1, 0, 0, 0, 0, 0, 0,
        1.0f, nullptr, bqkT + 4096, nullptr, 1);

    // GEMM 3: logits[z][c][d] = (1/32) Q·K ; z=b*4+h (zi=h, zo=b), fp32 out
    hgemm<<<dim3(NC / 128, NC / 128, 32), 256, GSMEM>>>(
        qkT, qkT + 2048LL * BT, attn, NT,
        BT, BT, NC,
        NH,
        512LL * BT, NT, 512LL * BT, NT,
        (long long)NC * NC, 4LL * NC * NC,
        1.0f / 32.0f, nullptr, nullptr, nullptr, 0);

    softmax512<<<32 * NC, 256>>>(attn, attnh);

    // GEMM 5: av2[b*1024+t][h*512+c] = sum_d V[t,d]·P[c,d]  (m=t, n=c)
    hgemm<<<dim3(NC / 128, NT / 128, 32), 256, GSMEM>>>(
        v2, attnh, av2, NC,
        NF, NC, NF,
        NH,
        512, (long long)NT * NF,
        (long long)NC * NC, 4LL * NC * NC,
        512, (long long)NT * NF,
        1.0f, nullptr, nullptr, nullptr, 1);

    // GEMM 6: out[b][t][c] = av2 @ woutT^T + b_out + x  (m=t, n=c, fp32 + resid)
    hgemm<<<dim3(NC / 128, NT / 128, NB), 256, GSMEM>>>(
        av2, woutT, out, NF,
        NF, NF, NC,
        1,
        0, (long long)NT * NF, 0, 0,
        0, (long long)NT * NC,
        1.0f, nullptr, b_out, x, 0);
}